// round 2
// baseline (speedup 1.0000x reference)
#include <cuda_runtime.h>
#include <cstdint>

#define BB   2
#define SS   2048
#define DD   1024
#define HH   16
#define HDIM 64
#define MTOT (BB*SS)          // 4096
#define SCALE_ATTN 0.125f     // 64^-0.5

// ---------------- scratch (device globals; no allocation allowed) ----------
__device__ float    g_Q[(size_t)BB*SS*DD];
__device__ float    g_K[(size_t)BB*SS*DD];
__device__ float    g_V[(size_t)BB*SS*DD];
__device__ float    g_AO[(size_t)BB*SS*DD];
__device__ unsigned g_packed[BB*SS];

// buffer tags so host code never needs cudaGetSymbolAddress
#define TAG_EXT (-1)
#define TAG_Q   0
#define TAG_K   1
#define TAG_V   2
#define TAG_AO  3

__device__ __forceinline__ float* pick_buf(int tag) {
    switch (tag) {
        case TAG_Q:  return g_Q;
        case TAG_K:  return g_K;
        case TAG_V:  return g_V;
        default:     return g_AO;
    }
}

// ---------------- id packing ----------------------------------------------
// field:0..4 (<32), entity:5..10 (<64), time:11..17 (<128), type:18..20 (<8),
// role:21..23 (<8), bit24 = edge!=0, bit25 = field==0 (pad)
#define MF   0x1Fu
#define ME   (0x3Fu<<5)
#define MT   (0x7Fu<<11)
#define MTT  (0x7u<<18)
#define MR   (0x7u<<21)
#define EDNZ (1u<<24)
#define PADB (1u<<25)

__global__ void pack_ids_kernel(const int* __restrict__ f, const int* __restrict__ e,
                                const int* __restrict__ t, const int* __restrict__ tt,
                                const int* __restrict__ ed, const int* __restrict__ r,
                                int n)
{
    int i = blockIdx.x * blockDim.x + threadIdx.x;
    if (i < n) {
        unsigned p = ((unsigned)f[i] & 31u)
                   | (((unsigned)e[i] & 63u) << 5)
                   | (((unsigned)t[i] & 127u) << 11)
                   | (((unsigned)tt[i] & 7u) << 18)
                   | (((unsigned)r[i] & 7u) << 21)
                   | ((ed[i] != 0) ? EDNZ : 0u)
                   | ((f[i] == 0) ? PADB : 0u);
        g_packed[i] = p;
    }
}

// ---------------- SGEMM (NT): Y[m,n] = sum_k X[m,k]*W[n,k] + bias[n] -------
// 128x128 tile, BK=8, 256 threads, 8x8 per thread, double-buffered smem.
// x_tag / y_tag select device-global scratch buffers; TAG_EXT uses the
// pointer argument (harness memory).
__global__ __launch_bounds__(256)
void sgemm_nt_bias(const float* __restrict__ X_ext, int x_tag,
                   const float* __restrict__ W, const float* __restrict__ bias,
                   float* __restrict__ Y_ext, int y_tag,
                   int M, int N, int K)
{
    const float* X = (x_tag == TAG_EXT) ? X_ext : pick_buf(x_tag);
    float*       Y = (y_tag == TAG_EXT) ? Y_ext : pick_buf(y_tag);

    __shared__ float Xs[2][8][128];
    __shared__ float Ws[2][8][128];

    const int t     = threadIdx.x;
    const int m_blk = blockIdx.y * 128;
    const int n_blk = blockIdx.x * 128;

    const int lr = t >> 1;          // 0..127 row within tile
    const int lk = (t & 1) * 4;     // 0 or 4

    const float* Xp = X + (size_t)(m_blk + lr) * K + lk;
    const float* Wp = W + (size_t)(n_blk + lr) * K + lk;

    const int ty = t >> 4;          // 0..15
    const int tx = t & 15;          // 0..15

    float acc[8][8];
#pragma unroll
    for (int i = 0; i < 8; i++)
#pragma unroll
        for (int j = 0; j < 8; j++) acc[i][j] = 0.f;

    // preload tile 0
    float4 xv = *(const float4*)Xp;
    float4 wv = *(const float4*)Wp;
    Xs[0][lk+0][lr] = xv.x; Xs[0][lk+1][lr] = xv.y; Xs[0][lk+2][lr] = xv.z; Xs[0][lk+3][lr] = xv.w;
    Ws[0][lk+0][lr] = wv.x; Ws[0][lk+1][lr] = wv.y; Ws[0][lk+2][lr] = wv.z; Ws[0][lk+3][lr] = wv.w;
    __syncthreads();

    const int nt = K / 8;
    int buf = 0;
    for (int kt = 0; kt < nt; kt++) {
        float4 xn, wn;
        const bool more = (kt + 1 < nt);
        if (more) {
            xn = *(const float4*)(Xp + (size_t)(kt + 1) * 8);
            wn = *(const float4*)(Wp + (size_t)(kt + 1) * 8);
        }
#pragma unroll
        for (int kk = 0; kk < 8; kk++) {
            float4 a0 = *(const float4*)&Xs[buf][kk][ty*8];
            float4 a1 = *(const float4*)&Xs[buf][kk][ty*8+4];
            float4 b0 = *(const float4*)&Ws[buf][kk][tx*8];
            float4 b1 = *(const float4*)&Ws[buf][kk][tx*8+4];
            float a[8] = {a0.x,a0.y,a0.z,a0.w,a1.x,a1.y,a1.z,a1.w};
            float b[8] = {b0.x,b0.y,b0.z,b0.w,b1.x,b1.y,b1.z,b1.w};
#pragma unroll
            for (int i = 0; i < 8; i++)
#pragma unroll
                for (int j = 0; j < 8; j++) acc[i][j] += a[i] * b[j];
        }
        if (more) {
            int nb = buf ^ 1;
            Xs[nb][lk+0][lr] = xn.x; Xs[nb][lk+1][lr] = xn.y; Xs[nb][lk+2][lr] = xn.z; Xs[nb][lk+3][lr] = xn.w;
            Ws[nb][lk+0][lr] = wn.x; Ws[nb][lk+1][lr] = wn.y; Ws[nb][lk+2][lr] = wn.z; Ws[nb][lk+3][lr] = wn.w;
        }
        __syncthreads();
        buf ^= 1;
    }

    float bb[8];
#pragma unroll
    for (int j = 0; j < 8; j++) bb[j] = bias[n_blk + tx*8 + j];

#pragma unroll
    for (int i = 0; i < 8; i++) {
        const int row = m_blk + ty*8 + i;
        float* yr = Y + (size_t)row * N + n_blk + tx*8;
        float4 o0, o1;
        o0.x = acc[i][0] + bb[0]; o0.y = acc[i][1] + bb[1];
        o0.z = acc[i][2] + bb[2]; o0.w = acc[i][3] + bb[3];
        o1.x = acc[i][4] + bb[4]; o1.y = acc[i][5] + bb[5];
        o1.z = acc[i][6] + bb[6]; o1.w = acc[i][7] + bb[7];
        *(float4*)(yr)     = o0;
        *(float4*)(yr + 4) = o1;
    }
}

// ---------------- fused bias attention (flash-style) -----------------------
// grid: (S/64, H, B); 256 threads; 64-query tile; KV streamed in 64 chunks.
// Reads g_Q/g_K/g_V/g_packed, writes g_AO directly (no pointer plumbing).
__global__ __launch_bounds__(256)
void attn_kernel()
{
    __shared__ float Qs[64][64];   // [k][row]
    __shared__ float KPs[64][64];  // phase A: [k][col] of K; phase B: P [row][col]
    __shared__ float Vs[64][64];   // [j][d]

    const int t  = threadIdx.x;
    const int mt = blockIdx.x;
    const int h  = blockIdx.y;
    const int b  = blockIdx.z;
    const int i0 = mt * 64;

    const float* Qg = g_Q + ((size_t)b * SS) * DD + h * HDIM;
    const float* Kg = g_K + ((size_t)b * SS) * DD + h * HDIM;
    const float* Vg = g_V + ((size_t)b * SS) * DD + h * HDIM;
    const unsigned* pk = g_packed + b * SS;

    const int ty = t >> 4, tx = t & 15;
    const int r0 = ty * 4, c0 = tx * 4;

    // load Q tile (transposed into [k][row])
#pragma unroll
    for (int rep = 0; rep < 4; rep++) {
        int idx = rep * 256 + t;           // float4 index 0..1023
        int row = idx >> 4;
        int v   = idx & 15;
        float4 q = *(const float4*)(Qg + (size_t)(i0 + row) * DD + v * 4);
        Qs[v*4+0][row] = q.x; Qs[v*4+1][row] = q.y;
        Qs[v*4+2][row] = q.z; Qs[v*4+3][row] = q.w;
    }

    unsigned rp[4];
#pragma unroll
    for (int i = 0; i < 4; i++) rp[i] = pk[i0 + r0 + i];

    float m_r[4], l_r[4], acc[4][4];
#pragma unroll
    for (int i = 0; i < 4; i++) {
        m_r[i] = -1e30f; l_r[i] = 0.f;
#pragma unroll
        for (int j = 0; j < 4; j++) acc[i][j] = 0.f;
    }

    for (int j0 = 0; j0 < SS; j0 += 64) {
        // load K (transposed) + V tiles
#pragma unroll
        for (int rep = 0; rep < 4; rep++) {
            int idx = rep * 256 + t;
            int row = idx >> 4;
            int v   = idx & 15;
            float4 kv4 = *(const float4*)(Kg + (size_t)(j0 + row) * DD + v * 4);
            KPs[v*4+0][row] = kv4.x; KPs[v*4+1][row] = kv4.y;
            KPs[v*4+2][row] = kv4.z; KPs[v*4+3][row] = kv4.w;
            float4 vv4 = *(const float4*)(Vg + (size_t)(j0 + row) * DD + v * 4);
            *(float4*)&Vs[row][v*4] = vv4;
        }
        __syncthreads();

        unsigned cp[4];
#pragma unroll
        for (int j = 0; j < 4; j++) cp[j] = pk[j0 + c0 + j];

        // step 1: S = Q K^T (4x4 register tile)
        float s[4][4];
#pragma unroll
        for (int i = 0; i < 4; i++)
#pragma unroll
            for (int j = 0; j < 4; j++) s[i][j] = 0.f;

#pragma unroll 16
        for (int kk = 0; kk < 64; kk++) {
            float4 a4 = *(const float4*)&Qs[kk][r0];
            float4 b4 = *(const float4*)&KPs[kk][c0];
            float a[4] = {a4.x, a4.y, a4.z, a4.w};
            float bv[4] = {b4.x, b4.y, b4.z, b4.w};
#pragma unroll
            for (int i = 0; i < 4; i++)
#pragma unroll
                for (int j = 0; j < 4; j++) s[i][j] += a[i] * bv[j];
        }

        // scale + structural bias from packed ids
#pragma unroll
        for (int i = 0; i < 4; i++) {
#pragma unroll
            for (int j = 0; j < 4; j++) {
                unsigned x = rp[i] ^ cp[j];
                unsigned o = rp[i] | cp[j];
                float bias = 0.f;
                if ((x & MF)  == 0u) bias += 1.0f;
                if ((x & ME)  == 0u) bias += 1.0f;
                if ((x & MT)  == 0u) bias += 0.5f;
                if ((x & MTT) == 0u) bias += 0.3f;
                if ((x & MR)  == 0u) bias += 0.5f;
                if (o & EDNZ)        bias += 1.5f;
                s[i][j] = (o & PADB) ? -1e30f : (s[i][j] * SCALE_ATTN + bias);
            }
        }
        __syncthreads();   // all done reading K from KPs

        // online softmax (per-row state replicated across the 16-thread group)
#pragma unroll
        for (int i = 0; i < 4; i++) {
            float mloc = fmaxf(fmaxf(s[i][0], s[i][1]), fmaxf(s[i][2], s[i][3]));
#pragma unroll
            for (int off = 1; off < 16; off <<= 1)
                mloc = fmaxf(mloc, __shfl_xor_sync(0xffffffffu, mloc, off));
            float mnew = fmaxf(m_r[i], mloc);
            float ps = 0.f;
#pragma unroll
            for (int j = 0; j < 4; j++) {
                float p = __expf(s[i][j] - mnew);
                s[i][j] = p;
                ps += p;
            }
#pragma unroll
            for (int off = 1; off < 16; off <<= 1)
                ps += __shfl_xor_sync(0xffffffffu, ps, off);
            float alpha = __expf(m_r[i] - mnew);
            l_r[i] = l_r[i] * alpha + ps;
            m_r[i] = mnew;
#pragma unroll
            for (int j = 0; j < 4; j++) acc[i][j] *= alpha;
        }

        // write P into KPs as [row][col]
#pragma unroll
        for (int i = 0; i < 4; i++)
#pragma unroll
            for (int j = 0; j < 4; j++) KPs[r0 + i][c0 + j] = s[i][j];
        __syncthreads();

        // step 3: acc += P @ V  (rows r0.., head-dims c0..)
#pragma unroll 8
        for (int j = 0; j < 64; j++) {
            float p0 = KPs[r0+0][j];
            float p1 = KPs[r0+1][j];
            float p2 = KPs[r0+2][j];
            float p3 = KPs[r0+3][j];
            float4 v4 = *(const float4*)&Vs[j][c0];
            float vv[4] = {v4.x, v4.y, v4.z, v4.w};
#pragma unroll
            for (int jj = 0; jj < 4; jj++) {
                acc[0][jj] += p0 * vv[jj];
                acc[1][jj] += p1 * vv[jj];
                acc[2][jj] += p2 * vv[jj];
                acc[3][jj] += p3 * vv[jj];
            }
        }
        __syncthreads();   // before next tile overwrites KPs/Vs
    }

    // normalize + write to g_AO [B,S,D] with head-major inner layout
#pragma unroll
    for (int i = 0; i < 4; i++) {
        float inv = 1.f / l_r[i];
        float4 o;
        o.x = acc[i][0] * inv; o.y = acc[i][1] * inv;
        o.z = acc[i][2] * inv; o.w = acc[i][3] * inv;
        *(float4*)(g_AO + (size_t)(b * SS + i0 + r0 + i) * DD + h * HDIM + c0) = o;
    }
}

// ---------------- launch ----------------------------------------------------
extern "C" void kernel_launch(void* const* d_in, const int* in_sizes, int n_in,
                              void* d_out, int out_size)
{
    (void)in_sizes; (void)n_in; (void)out_size;
    const float* query = (const float*)d_in[0];
    const float* key_  = (const float*)d_in[1];
    const float* value = (const float*)d_in[2];
    const int* fid = (const int*)d_in[3];
    const int* eid = (const int*)d_in[4];
    const int* tid = (const int*)d_in[5];
    const int* ttd = (const int*)d_in[6];
    const int* edd = (const int*)d_in[7];
    const int* rid = (const int*)d_in[8];
    const float* Wq = (const float*)d_in[9];
    const float* bq = (const float*)d_in[10];
    const float* Wk = (const float*)d_in[11];
    const float* bk = (const float*)d_in[12];
    const float* Wv = (const float*)d_in[13];
    const float* bv = (const float*)d_in[14];
    const float* Wo = (const float*)d_in[15];
    const float* bo = (const float*)d_in[16];
    float* out = (float*)d_out;

    dim3 gemm_grid(DD / 128, MTOT / 128);   // (8, 32)

    sgemm_nt_bias<<<gemm_grid, 256>>>(query, TAG_EXT, Wq, bq, nullptr, TAG_Q,  MTOT, DD, DD);
    sgemm_nt_bias<<<gemm_grid, 256>>>(key_,  TAG_EXT, Wk, bk, nullptr, TAG_K,  MTOT, DD, DD);
    sgemm_nt_bias<<<gemm_grid, 256>>>(value, TAG_EXT, Wv, bv, nullptr, TAG_V,  MTOT, DD, DD);

    pack_ids_kernel<<<(BB * SS + 255) / 256, 256>>>(fid, eid, tid, ttd, edd, rid, BB * SS);

    attn_kernel<<<dim3(SS / 64, HH, BB), 256>>>();

    sgemm_nt_bias<<<gemm_grid, 256>>>(nullptr, TAG_AO, Wo, bo, out, TAG_EXT, MTOT, DD, DD);
}

// round 4
// speedup vs baseline: 1.3664x; 1.3664x over previous
#include <cuda_runtime.h>
#include <cstdint>

#define BB   2
#define SS   2048
#define DD   1024
#define HH   16
#define HDIM 64
#define MTOT (BB*SS)          // 4096
#define SCALE_ATTN 0.125f     // 64^-0.5

// ---------------- scratch (device globals; no allocation allowed) ----------
__device__ float    g_Q[(size_t)BB*SS*DD];
__device__ float    g_K[(size_t)BB*SS*DD];
__device__ float    g_V[(size_t)BB*SS*DD];
__device__ float    g_AO[(size_t)BB*SS*DD];
__device__ unsigned g_packed[BB*SS];

#define TAG_EXT (-1)
#define TAG_Q   0
#define TAG_K   1
#define TAG_V   2
#define TAG_AO  3

__device__ __forceinline__ float* pick_buf(int tag) {
    switch (tag) {
        case TAG_Q:  return g_Q;
        case TAG_K:  return g_K;
        case TAG_V:  return g_V;
        default:     return g_AO;
    }
}

// ---------------- id packing ----------------------------------------------
#define MF   0x1Fu
#define ME   (0x3Fu<<5)
#define MT   (0x7Fu<<11)
#define MTT  (0x7u<<18)
#define MR   (0x7u<<21)
#define EDNZ (1u<<24)
#define PADB (1u<<25)

__global__ void pack_ids_kernel(const int* __restrict__ f, const int* __restrict__ e,
                                const int* __restrict__ t, const int* __restrict__ tt,
                                const int* __restrict__ ed, const int* __restrict__ r,
                                int n)
{
    int i = blockIdx.x * blockDim.x + threadIdx.x;
    if (i < n) {
        unsigned p = ((unsigned)f[i] & 31u)
                   | (((unsigned)e[i] & 63u) << 5)
                   | (((unsigned)t[i] & 127u) << 11)
                   | (((unsigned)tt[i] & 7u) << 18)
                   | (((unsigned)r[i] & 7u) << 21)
                   | ((ed[i] != 0) ? EDNZ : 0u)
                   | ((f[i] == 0) ? PADB : 0u);
        g_packed[i] = p;
    }
}

// ---------------- tf32 mma helpers -----------------------------------------
__device__ __forceinline__ void split_tf32(float x, unsigned& hi, unsigned& lo) {
    unsigned h; asm("cvt.rna.tf32.f32 %0, %1;" : "=r"(h) : "f"(x));
    float res = x - __uint_as_float(h);
    unsigned l; asm("cvt.rna.tf32.f32 %0, %1;" : "=r"(l) : "f"(res));
    hi = h; lo = l;
}

__device__ __forceinline__ void mma_tf32(float c[4], const unsigned a[4],
                                         unsigned b0, unsigned b1) {
    asm volatile(
        "mma.sync.aligned.m16n8k8.row.col.f32.tf32.tf32.f32 "
        "{%0,%1,%2,%3},{%4,%5,%6,%7},{%8,%9},{%0,%1,%2,%3};"
        : "+f"(c[0]), "+f"(c[1]), "+f"(c[2]), "+f"(c[3])
        : "r"(a[0]), "r"(a[1]), "r"(a[2]), "r"(a[3]), "r"(b0), "r"(b1));
}

// ---------------- GEMM (NT, split-tf32): Y = X W^T + bias ------------------
// block 128x128, BK=32, 8 warps each 32(M)x64(N); smem stride 36 (conflict-free)
__global__ __launch_bounds__(256, 1)
void sgemm_tf32(const float* __restrict__ X_ext, int x_tag,
                const float* __restrict__ W, const float* __restrict__ bias,
                float* __restrict__ Y_ext, int y_tag)
{
    const float* X = (x_tag == TAG_EXT) ? X_ext : pick_buf(x_tag);
    float*       Y = (y_tag == TAG_EXT) ? Y_ext : pick_buf(y_tag);
    const int K = DD, N = DD;

    __shared__ float Xs[128][36];
    __shared__ float Ws[128][36];

    const int t    = threadIdx.x;
    const int m_blk = blockIdx.y * 128;
    const int n_blk = blockIdx.x * 128;
    const int w    = t >> 5, lane = t & 31;
    const int g    = lane >> 2, tig = lane & 3;
    const int wm   = w & 3,  wn  = w >> 2;

    const int lrow = t >> 3;        // 0..31
    const int lcol = (t & 7) * 4;   // 0..28

    const float* Xg = X + (size_t)(m_blk + lrow) * K + lcol;
    const float* Wg = W + (size_t)(n_blk + lrow) * K + lcol;

    float4 xbuf[4], wbuf[4];
#pragma unroll
    for (int i = 0; i < 4; i++) {
        xbuf[i] = *(const float4*)(Xg + (size_t)(32 * i) * K);
        wbuf[i] = *(const float4*)(Wg + (size_t)(32 * i) * K);
    }

    float acc[2][8][4];
#pragma unroll
    for (int mt = 0; mt < 2; mt++)
#pragma unroll
        for (int nt = 0; nt < 8; nt++)
#pragma unroll
            for (int i = 0; i < 4; i++) acc[mt][nt][i] = 0.f;

    for (int kt = 0; kt < 32; kt++) {
#pragma unroll
        for (int i = 0; i < 4; i++) {
            *(float4*)&Xs[lrow + 32 * i][lcol] = xbuf[i];
            *(float4*)&Ws[lrow + 32 * i][lcol] = wbuf[i];
        }
        __syncthreads();
        if (kt < 31) {
#pragma unroll
            for (int i = 0; i < 4; i++) {
                xbuf[i] = *(const float4*)(Xg + (size_t)(32 * i) * K + (kt + 1) * 32);
                wbuf[i] = *(const float4*)(Wg + (size_t)(32 * i) * K + (kt + 1) * 32);
            }
        }
#pragma unroll
        for (int ks = 0; ks < 4; ks++) {
            const int k8 = ks * 8;
            unsigned ah[2][4], al[2][4];
#pragma unroll
            for (int mt = 0; mt < 2; mt++) {
                const int r0 = wm * 32 + mt * 16;
                split_tf32(Xs[r0 + g    ][k8 + tig    ], ah[mt][0], al[mt][0]);
                split_tf32(Xs[r0 + 8 + g][k8 + tig    ], ah[mt][1], al[mt][1]);
                split_tf32(Xs[r0 + g    ][k8 + tig + 4], ah[mt][2], al[mt][2]);
                split_tf32(Xs[r0 + 8 + g][k8 + tig + 4], ah[mt][3], al[mt][3]);
            }
#pragma unroll
            for (int nt = 0; nt < 8; nt++) {
                const int c0 = wn * 64 + nt * 8 + g;
                unsigned bh0, bl0, bh1, bl1;
                split_tf32(Ws[c0][k8 + tig    ], bh0, bl0);
                split_tf32(Ws[c0][k8 + tig + 4], bh1, bl1);
#pragma unroll
                for (int mt = 0; mt < 2; mt++) {
                    mma_tf32(acc[mt][nt], ah[mt], bh0, bh1);
                    mma_tf32(acc[mt][nt], al[mt], bh0, bh1);
                    mma_tf32(acc[mt][nt], ah[mt], bl0, bl1);
                }
            }
        }
        __syncthreads();
    }

#pragma unroll
    for (int mt = 0; mt < 2; mt++) {
        const int row0 = m_blk + wm * 32 + mt * 16 + g;
#pragma unroll
        for (int nt = 0; nt < 8; nt++) {
            const int col = n_blk + wn * 64 + nt * 8 + tig * 2;
            const float b0 = bias[col], b1 = bias[col + 1];
            float2 v0, v1;
            v0.x = acc[mt][nt][0] + b0; v0.y = acc[mt][nt][1] + b1;
            v1.x = acc[mt][nt][2] + b0; v1.y = acc[mt][nt][3] + b1;
            *(float2*)(Y + (size_t)row0 * N + col)       = v0;
            *(float2*)(Y + (size_t)(row0 + 8) * N + col) = v1;
        }
    }
}

// ---------------- structural bias -----------------------------------------
__device__ __forceinline__ float sbias(float s, unsigned a, unsigned bId) {
    const unsigned x = a ^ bId, o = a | bId;
    float bias = 0.f;
    if ((x & MF)  == 0u) bias += 1.0f;
    if ((x & ME)  == 0u) bias += 1.0f;
    if ((x & MT)  == 0u) bias += 0.5f;
    if ((x & MTT) == 0u) bias += 0.3f;
    if ((x & MR)  == 0u) bias += 0.5f;
    if (o & EDNZ)        bias += 1.5f;
    const float v = s * SCALE_ATTN + bias;
    return (o & PADB) ? -1e30f : v;
}

// ---------------- fused attention (split-tf32 mma, flash-style) ------------
// block: 128 queries x 1 head x 1 batch; 8 warps, each warp = 16 rows x full width
__global__ __launch_bounds__(256, 1)
void attn_tf32()
{
    __shared__ float Ks[64][68];
    __shared__ float Vs[64][68];
    __shared__ unsigned pk_s[64];

    const int t = threadIdx.x, w = t >> 5, lane = t & 31;
    const int g = lane >> 2, tig = lane & 3;
    const int qb = blockIdx.x * 128;
    const int h  = blockIdx.y, b = blockIdx.z;
    const int row_g = qb + w * 16 + g;     // query row within sequence

    const float* Qbase = g_Q + (size_t)(b * SS) * DD + h * HDIM;
    const float* Kbase = g_K + (size_t)(b * SS) * DD + h * HDIM;
    const float* Vbase = g_V + (size_t)(b * SS) * DD + h * HDIM;

    // persistent Q A-fragments (hi/lo split)
    unsigned qh[8][4], ql[8][4];
#pragma unroll
    for (int ks = 0; ks < 8; ks++) {
        split_tf32(Qbase[(size_t)row_g       * DD + ks * 8 + tig    ], qh[ks][0], ql[ks][0]);
        split_tf32(Qbase[(size_t)(row_g + 8) * DD + ks * 8 + tig    ], qh[ks][1], ql[ks][1]);
        split_tf32(Qbase[(size_t)row_g       * DD + ks * 8 + tig + 4], qh[ks][2], ql[ks][2]);
        split_tf32(Qbase[(size_t)(row_g + 8) * DD + ks * 8 + tig + 4], qh[ks][3], ql[ks][3]);
    }

    const unsigned rp0 = g_packed[b * SS + row_g];
    const unsigned rp1 = g_packed[b * SS + row_g + 8];

    float m0 = -1e30f, m1 = -1e30f, l0 = 0.f, l1 = 0.f;
    float O[8][4];
#pragma unroll
    for (int nt = 0; nt < 8; nt++)
#pragma unroll
        for (int i = 0; i < 4; i++) O[nt][i] = 0.f;

    for (int j0 = 0; j0 < SS; j0 += 64) {
        __syncthreads();   // previous iteration's smem reads complete
#pragma unroll
        for (int i = 0; i < 4; i++) {
            const int r = (t >> 4) + i * 16;
            const int c = (t & 15) * 4;
            *(float4*)&Ks[r][c] = *(const float4*)(Kbase + (size_t)(j0 + r) * DD + c);
            *(float4*)&Vs[r][c] = *(const float4*)(Vbase + (size_t)(j0 + r) * DD + c);
        }
        if (t < 64) pk_s[t] = g_packed[b * SS + j0 + t];
        __syncthreads();

        // S = Q K^T (64 keys), split-tf32
        float S[8][4];
#pragma unroll
        for (int nt = 0; nt < 8; nt++) {
#pragma unroll
            for (int i = 0; i < 4; i++) S[nt][i] = 0.f;
#pragma unroll
            for (int ks = 0; ks < 8; ks++) {
                unsigned bh0, bl0, bh1, bl1;
                split_tf32(Ks[nt * 8 + g][ks * 8 + tig    ], bh0, bl0);
                split_tf32(Ks[nt * 8 + g][ks * 8 + tig + 4], bh1, bl1);
                mma_tf32(S[nt], qh[ks], bh0, bh1);
                mma_tf32(S[nt], ql[ks], bh0, bh1);
                mma_tf32(S[nt], qh[ks], bl0, bl1);
            }
        }

        // bias + row max
        float mloc0 = -1e30f, mloc1 = -1e30f;
#pragma unroll
        for (int nt = 0; nt < 8; nt++) {
            const unsigned cp0 = pk_s[nt * 8 + tig * 2];
            const unsigned cp1 = pk_s[nt * 8 + tig * 2 + 1];
            S[nt][0] = sbias(S[nt][0], rp0, cp0);
            S[nt][1] = sbias(S[nt][1], rp0, cp1);
            S[nt][2] = sbias(S[nt][2], rp1, cp0);
            S[nt][3] = sbias(S[nt][3], rp1, cp1);
            mloc0 = fmaxf(mloc0, fmaxf(S[nt][0], S[nt][1]));
            mloc1 = fmaxf(mloc1, fmaxf(S[nt][2], S[nt][3]));
        }
        mloc0 = fmaxf(mloc0, __shfl_xor_sync(0xffffffffu, mloc0, 1));
        mloc0 = fmaxf(mloc0, __shfl_xor_sync(0xffffffffu, mloc0, 2));
        mloc1 = fmaxf(mloc1, __shfl_xor_sync(0xffffffffu, mloc1, 1));
        mloc1 = fmaxf(mloc1, __shfl_xor_sync(0xffffffffu, mloc1, 2));

        const float mn0 = fmaxf(m0, mloc0), mn1 = fmaxf(m1, mloc1);
        float ps0 = 0.f, ps1 = 0.f;
#pragma unroll
        for (int nt = 0; nt < 8; nt++) {
            S[nt][0] = __expf(S[nt][0] - mn0); ps0 += S[nt][0];
            S[nt][1] = __expf(S[nt][1] - mn0); ps0 += S[nt][1];
            S[nt][2] = __expf(S[nt][2] - mn1); ps1 += S[nt][2];
            S[nt][3] = __expf(S[nt][3] - mn1); ps1 += S[nt][3];
        }
        ps0 += __shfl_xor_sync(0xffffffffu, ps0, 1);
        ps0 += __shfl_xor_sync(0xffffffffu, ps0, 2);
        ps1 += __shfl_xor_sync(0xffffffffu, ps1, 1);
        ps1 += __shfl_xor_sync(0xffffffffu, ps1, 2);

        const float al0 = __expf(m0 - mn0), al1 = __expf(m1 - mn1);
        l0 = l0 * al0 + ps0;  l1 = l1 * al1 + ps1;
        m0 = mn0; m1 = mn1;
#pragma unroll
        for (int nt = 0; nt < 8; nt++) {
            O[nt][0] *= al0; O[nt][1] *= al0;
            O[nt][2] *= al1; O[nt][3] *= al1;
        }

        // PV: remap P C-frags -> A-frags via quad shuffles, then mma with V
#pragma unroll
        for (int kk = 0; kk < 8; kk++) {
            const int srcA = (lane & 28) | (tig >> 1);
            const int srcB = srcA + 2;
            const float x0 = __shfl_sync(0xffffffffu, S[kk][0], srcA);
            const float x1 = __shfl_sync(0xffffffffu, S[kk][1], srcA);
            const float x2 = __shfl_sync(0xffffffffu, S[kk][2], srcA);
            const float x3 = __shfl_sync(0xffffffffu, S[kk][3], srcA);
            const float y0 = __shfl_sync(0xffffffffu, S[kk][0], srcB);
            const float y1 = __shfl_sync(0xffffffffu, S[kk][1], srcB);
            const float y2 = __shfl_sync(0xffffffffu, S[kk][2], srcB);
            const float y3 = __shfl_sync(0xffffffffu, S[kk][3], srcB);
            const bool odd = (tig & 1);
            unsigned pah[4], pal[4];
            split_tf32(odd ? x1 : x0, pah[0], pal[0]);   // (g,    kk*8+tig)
            split_tf32(odd ? x3 : x2, pah[1], pal[1]);   // (g+8,  kk*8+tig)
            split_tf32(odd ? y1 : y0, pah[2], pal[2]);   // (g,    kk*8+tig+4)
            split_tf32(odd ? y3 : y2, pah[3], pal[3]);   // (g+8,  kk*8+tig+4)
#pragma unroll
            for (int nt = 0; nt < 8; nt++) {
                unsigned vh0, vl0, vh1, vl1;
                split_tf32(Vs[kk * 8 + tig    ][nt * 8 + g], vh0, vl0);
                split_tf32(Vs[kk * 8 + tig + 4][nt * 8 + g], vh1, vl1);
                mma_tf32(O[nt], pah, vh0, vh1);
                mma_tf32(O[nt], pal, vh0, vh1);
                mma_tf32(O[nt], pah, vl0, vl1);
            }
        }
    }

    const float inv0 = 1.f / l0, inv1 = 1.f / l1;
    float* Obase = g_AO + (size_t)(b * SS) * DD + h * HDIM;
#pragma unroll
    for (int nt = 0; nt < 8; nt++) {
        const int col = nt * 8 + tig * 2;
        float2 o0, o1;
        o0.x = O[nt][0] * inv0; o0.y = O[nt][1] * inv0;
        o1.x = O[nt][2] * inv1; o1.y = O[nt][3] * inv1;
        *(float2*)(Obase + (size_t)row_g       * DD + col) = o0;
        *(float2*)(Obase + (size_t)(row_g + 8) * DD + col) = o1;
    }
}

// ---------------- launch ----------------------------------------------------
extern "C" void kernel_launch(void* const* d_in, const int* in_sizes, int n_in,
                              void* d_out, int out_size)
{
    (void)in_sizes; (void)n_in; (void)out_size;
    const float* query = (const float*)d_in[0];
    const float* key_  = (const float*)d_in[1];
    const float* value = (const float*)d_in[2];
    const int* fid = (const int*)d_in[3];
    const int* eid = (const int*)d_in[4];
    const int* tid = (const int*)d_in[5];
    const int* ttd = (const int*)d_in[6];
    const int* edd = (const int*)d_in[7];
    const int* rid = (const int*)d_in[8];
    const float* Wq = (const float*)d_in[9];
    const float* bq = (const float*)d_in[10];
    const float* Wk = (const float*)d_in[11];
    const float* bk = (const float*)d_in[12];
    const float* Wv = (const float*)d_in[13];
    const float* bv = (const float*)d_in[14];
    const float* Wo = (const float*)d_in[15];
    const float* bo = (const float*)d_in[16];
    float* out = (float*)d_out;

    dim3 gemm_grid(DD / 128, MTOT / 128);   // (8, 32)

    sgemm_tf32<<<gemm_grid, 256>>>(query, TAG_EXT, Wq, bq, nullptr, TAG_Q);
    sgemm_tf32<<<gemm_grid, 256>>>(key_,  TAG_EXT, Wk, bk, nullptr, TAG_K);
    sgemm_tf32<<<gemm_grid, 256>>>(value, TAG_EXT, Wv, bv, nullptr, TAG_V);

    pack_ids_kernel<<<(BB * SS + 255) / 256, 256>>>(fid, eid, tid, ttd, edd, rid, BB * SS);

    attn_tf32<<<dim3(SS / 128, HH, BB), 256>>>();

    sgemm_tf32<<<gemm_grid, 256>>>(nullptr, TAG_AO, Wo, bo, out, TAG_EXT);
}

// round 5
// speedup vs baseline: 2.4932x; 1.8246x over previous
#include <cuda_runtime.h>
#include <cuda_bf16.h>
#include <cstdint>

#define BB   2
#define SS   2048
#define DD   1024
#define DD2  512
#define HH   16
#define HDIM 64
#define MTOT (BB*SS)          // 4096
#define SCALE_ATTN 0.125f

// ---------------- scratch (device globals; no allocation allowed) ----------
// Q, K stored as packed bf16x2 hi/lo pairs along the feature dim.
__device__ unsigned g_Qh[(size_t)MTOT*DD2];
__device__ unsigned g_Ql[(size_t)MTOT*DD2];
__device__ unsigned g_Kh[(size_t)MTOT*DD2];
__device__ unsigned g_Kl[(size_t)MTOT*DD2];
// V stored key-pair-packed: element (sp, d) = pack(V[2sp][d], V[2sp+1][d])
__device__ unsigned g_VkPh[(size_t)(MTOT/2)*DD];
__device__ unsigned g_VkPl[(size_t)(MTOT/2)*DD];
__device__ float    g_AO[(size_t)MTOT*DD];
__device__ unsigned g_packed[MTOT];

#define TAG_EXT (-1)
#define TAG_Q   0
#define TAG_K   1
#define TAG_V   2
#define TAG_AO  3

// ---------------- id packing ----------------------------------------------
#define MF   0x1Fu
#define ME   (0x3Fu<<5)
#define MT   (0x7Fu<<11)
#define MTT  (0x7u<<18)
#define MR   (0x7u<<21)
#define EDNZ (1u<<24)
#define PADB (1u<<25)

__global__ void pack_ids_kernel(const int* __restrict__ f, const int* __restrict__ e,
                                const int* __restrict__ t, const int* __restrict__ tt,
                                const int* __restrict__ ed, const int* __restrict__ r,
                                int n)
{
    int i = blockIdx.x * blockDim.x + threadIdx.x;
    if (i < n) {
        unsigned p = ((unsigned)f[i] & 31u)
                   | (((unsigned)e[i] & 63u) << 5)
                   | (((unsigned)t[i] & 127u) << 11)
                   | (((unsigned)tt[i] & 7u) << 18)
                   | (((unsigned)r[i] & 7u) << 21)
                   | ((ed[i] != 0) ? EDNZ : 0u)
                   | ((f[i] == 0) ? PADB : 0u);
        g_packed[i] = p;
    }
}

// ---------------- bf16 split helpers ---------------------------------------
__device__ __forceinline__ void split2(float a, float b, unsigned& h, unsigned& l) {
    __nv_bfloat162 hh = __floats2bfloat162_rn(a, b);   // .x = a (low 16 bits)
    float ra = a - __bfloat162float(hh.x);
    float rb = b - __bfloat162float(hh.y);
    __nv_bfloat162 ll = __floats2bfloat162_rn(ra, rb);
    h = *(unsigned*)&hh;
    l = *(unsigned*)&ll;
}

__device__ __forceinline__ void mma_bf16(float c[4], const unsigned a[4],
                                         unsigned b0, unsigned b1) {
    asm volatile(
        "mma.sync.aligned.m16n8k16.row.col.f32.bf16.bf16.f32 "
        "{%0,%1,%2,%3},{%4,%5,%6,%7},{%8,%9},{%0,%1,%2,%3};"
        : "+f"(c[0]), "+f"(c[1]), "+f"(c[2]), "+f"(c[3])
        : "r"(a[0]), "r"(a[1]), "r"(a[2]), "r"(a[3]), "r"(b0), "r"(b1));
}

// ---------------- GEMM (NT, bf16x2 3-product): Y = scale*(X W^T + bias) ----
// block 128x128, BK=32 (16 bf16x2 pairs), 8 warps each 32(M)x64(N).
// Inputs split ONCE at smem-store. Epilogue writes float, dim-packed split
// (Q scaled / K), or key-pair-packed split (V).
__global__ __launch_bounds__(256, 1)
void gemm_bf16x2(const float* __restrict__ X_ext, int x_tag,
                 const float* __restrict__ W, const float* __restrict__ bias,
                 float* __restrict__ Y_ext, int y_tag, float out_scale)
{
    const float* X = (x_tag == TAG_EXT) ? X_ext : g_AO;

    __shared__ unsigned XsH[128][20], XsL[128][20];
    __shared__ unsigned WsH[128][20], WsL[128][20];

    const int t = threadIdx.x;
    const int m_blk = blockIdx.y * 128;
    const int n_blk = blockIdx.x * 128;
    const int w = t >> 5, lane = t & 31;
    const int g = lane >> 2, tig = lane & 3;
    const int wm = w & 3, wn = w >> 2;

    int lrow[4], lf4[4];
#pragma unroll
    for (int i = 0; i < 4; i++) { int idx = i * 256 + t; lrow[i] = idx >> 3; lf4[i] = idx & 7; }

    float4 xb[4], wb[4];
#pragma unroll
    for (int i = 0; i < 4; i++) {
        xb[i] = *(const float4*)(X + (size_t)(m_blk + lrow[i]) * DD + lf4[i] * 4);
        wb[i] = *(const float4*)(W + (size_t)(n_blk + lrow[i]) * DD + lf4[i] * 4);
    }

    float acc[2][8][4];
#pragma unroll
    for (int mt = 0; mt < 2; mt++)
#pragma unroll
        for (int nt = 0; nt < 8; nt++)
#pragma unroll
            for (int i = 0; i < 4; i++) acc[mt][nt][i] = 0.f;

    for (int kt = 0; kt < 32; kt++) {
#pragma unroll
        for (int i = 0; i < 4; i++) {
            unsigned h0, l0, h1, l1;
            split2(xb[i].x, xb[i].y, h0, l0);
            split2(xb[i].z, xb[i].w, h1, l1);
            *(uint2*)&XsH[lrow[i]][lf4[i] * 2] = make_uint2(h0, h1);
            *(uint2*)&XsL[lrow[i]][lf4[i] * 2] = make_uint2(l0, l1);
            split2(wb[i].x, wb[i].y, h0, l0);
            split2(wb[i].z, wb[i].w, h1, l1);
            *(uint2*)&WsH[lrow[i]][lf4[i] * 2] = make_uint2(h0, h1);
            *(uint2*)&WsL[lrow[i]][lf4[i] * 2] = make_uint2(l0, l1);
        }
        __syncthreads();
        if (kt < 31) {
#pragma unroll
            for (int i = 0; i < 4; i++) {
                xb[i] = *(const float4*)(X + (size_t)(m_blk + lrow[i]) * DD + (kt + 1) * 32 + lf4[i] * 4);
                wb[i] = *(const float4*)(W + (size_t)(n_blk + lrow[i]) * DD + (kt + 1) * 32 + lf4[i] * 4);
            }
        }
#pragma unroll
        for (int ks = 0; ks < 2; ks++) {
            const int p0 = ks * 8;
            unsigned ah[2][4], al[2][4];
#pragma unroll
            for (int mt = 0; mt < 2; mt++) {
                const int r0 = wm * 32 + mt * 16;
                ah[mt][0] = XsH[r0 + g    ][p0 + tig];
                ah[mt][1] = XsH[r0 + 8 + g][p0 + tig];
                ah[mt][2] = XsH[r0 + g    ][p0 + 4 + tig];
                ah[mt][3] = XsH[r0 + 8 + g][p0 + 4 + tig];
                al[mt][0] = XsL[r0 + g    ][p0 + tig];
                al[mt][1] = XsL[r0 + 8 + g][p0 + tig];
                al[mt][2] = XsL[r0 + g    ][p0 + 4 + tig];
                al[mt][3] = XsL[r0 + 8 + g][p0 + 4 + tig];
            }
#pragma unroll
            for (int nt = 0; nt < 8; nt++) {
                const int c0 = wn * 64 + nt * 8 + g;
                const unsigned bh0 = WsH[c0][p0 + tig];
                const unsigned bh1 = WsH[c0][p0 + 4 + tig];
                const unsigned bl0 = WsL[c0][p0 + tig];
                const unsigned bl1 = WsL[c0][p0 + 4 + tig];
#pragma unroll
                for (int mt = 0; mt < 2; mt++) {
                    mma_bf16(acc[mt][nt], ah[mt], bh0, bh1);
                    mma_bf16(acc[mt][nt], al[mt], bh0, bh1);
                    mma_bf16(acc[mt][nt], ah[mt], bl0, bl1);
                }
            }
        }
        __syncthreads();
    }

    // ---------------- epilogue ----------------
    unsigned* Yh = (y_tag == TAG_Q) ? g_Qh : g_Kh;
    unsigned* Yl = (y_tag == TAG_Q) ? g_Ql : g_Kl;

#pragma unroll
    for (int mt = 0; mt < 2; mt++) {
        const int row0 = m_blk + wm * 32 + mt * 16 + g;
#pragma unroll
        for (int nt = 0; nt < 8; nt++) {
            const int col = n_blk + wn * 64 + nt * 8 + tig * 2;
            const float b0 = bias[col], b1 = bias[col + 1];
            float v0 = (acc[mt][nt][0] + b0) * out_scale;
            float v1 = (acc[mt][nt][1] + b1) * out_scale;
            float v2 = (acc[mt][nt][2] + b0) * out_scale;
            float v3 = (acc[mt][nt][3] + b1) * out_scale;

            if (y_tag == TAG_EXT) {
                float2 o0, o1;
                o0.x = v0; o0.y = v1; o1.x = v2; o1.y = v3;
                *(float2*)(Y_ext + (size_t)row0 * DD + col)       = o0;
                *(float2*)(Y_ext + (size_t)(row0 + 8) * DD + col) = o1;
            } else if (y_tag == TAG_V) {
                // key-pair repack: pair rows (2a, 2a+1). lane^4 flips g parity.
                float p0 = __shfl_xor_sync(0xffffffffu, v0, 4);
                float p1 = __shfl_xor_sync(0xffffffffu, v1, 4);
                float p2 = __shfl_xor_sync(0xffffffffu, v2, 4);
                float p3 = __shfl_xor_sync(0xffffffffu, v3, 4);
                if (!(g & 1)) {
                    unsigned h0, l0, h1, l1, h2, l2, h3, l3;
                    split2(v0, p0, h0, l0);   // (row, row+1) at col
                    split2(v1, p1, h1, l1);   // at col+1
                    split2(v2, p2, h2, l2);   // rows +8,+9 at col
                    split2(v3, p3, h3, l3);
                    const size_t i0 = (size_t)(row0 >> 1) * DD + col;
                    const size_t i1 = (size_t)((row0 + 8) >> 1) * DD + col;
                    *(uint2*)&g_VkPh[i0] = make_uint2(h0, h1);
                    *(uint2*)&g_VkPl[i0] = make_uint2(l0, l1);
                    *(uint2*)&g_VkPh[i1] = make_uint2(h2, h3);
                    *(uint2*)&g_VkPl[i1] = make_uint2(l2, l3);
                }
            } else {
                // dim-packed split (Q or K)
                unsigned h0, l0, h1, l1;
                split2(v0, v1, h0, l0);
                split2(v2, v3, h1, l1);
                const size_t i0 = (size_t)row0 * DD2 + (col >> 1);
                const size_t i1 = (size_t)(row0 + 8) * DD2 + (col >> 1);
                Yh[i0] = h0; Yl[i0] = l0;
                Yh[i1] = h1; Yl[i1] = l1;
            }
        }
    }
}

// ---------------- structural bias (Q pre-scaled, so no score scale) --------
__device__ __forceinline__ float sbias(float s, unsigned a, unsigned bId) {
    const unsigned x = a ^ bId, o = a | bId;
    float bias = 0.f;
    if ((x & MF)  == 0u) bias += 1.0f;
    if ((x & ME)  == 0u) bias += 1.0f;
    if ((x & MT)  == 0u) bias += 0.5f;
    if ((x & MTT) == 0u) bias += 0.3f;
    if ((x & MR)  == 0u) bias += 0.5f;
    if (o & EDNZ)        bias += 1.5f;
    const float v = s + bias;
    return (o & PADB) ? -1e30f : v;
}

// ---------------- fused attention (bf16x2 mma, all operands pre-split) -----
// block: 128 queries x 1 head x 1 batch; 8 warps x 16 rows; 64-key tiles.
__global__ __launch_bounds__(256, 1)
void attn_bf16()
{
    __shared__ unsigned KsH[64][36], KsL[64][36];   // [key][dim-pair]
    __shared__ unsigned VsH[32][72], VsL[32][72];   // [key-pair][dim]
    __shared__ unsigned pk_s[64];

    const int t = threadIdx.x, w = t >> 5, lane = t & 31;
    const int g = lane >> 2, tig = lane & 3;
    const int qb = blockIdx.x * 128;
    const int h  = blockIdx.y, b = blockIdx.z;
    const int row_g = qb + w * 16 + g;

    const unsigned* Qh = g_Qh + (size_t)b * SS * DD2 + h * 32;
    const unsigned* Ql = g_Ql + (size_t)b * SS * DD2 + h * 32;
    const unsigned* Kh = g_Kh + (size_t)b * SS * DD2 + h * 32;
    const unsigned* Kl = g_Kl + (size_t)b * SS * DD2 + h * 32;
    const unsigned* Vh = g_VkPh + (size_t)b * (SS / 2) * DD + h * 64;
    const unsigned* Vl = g_VkPl + (size_t)b * (SS / 2) * DD + h * 64;

    // persistent Q fragments (pre-split, pre-scaled)
    unsigned qh[4][4], ql[4][4];
#pragma unroll
    for (int ks = 0; ks < 4; ks++) {
        qh[ks][0] = Qh[(size_t)row_g       * DD2 + ks * 8 + tig];
        qh[ks][1] = Qh[(size_t)(row_g + 8) * DD2 + ks * 8 + tig];
        qh[ks][2] = Qh[(size_t)row_g       * DD2 + ks * 8 + 4 + tig];
        qh[ks][3] = Qh[(size_t)(row_g + 8) * DD2 + ks * 8 + 4 + tig];
        ql[ks][0] = Ql[(size_t)row_g       * DD2 + ks * 8 + tig];
        ql[ks][1] = Ql[(size_t)(row_g + 8) * DD2 + ks * 8 + tig];
        ql[ks][2] = Ql[(size_t)row_g       * DD2 + ks * 8 + 4 + tig];
        ql[ks][3] = Ql[(size_t)(row_g + 8) * DD2 + ks * 8 + 4 + tig];
    }

    const unsigned rp0 = g_packed[b * SS + row_g];
    const unsigned rp1 = g_packed[b * SS + row_g + 8];

    float m0 = -1e30f, m1 = -1e30f, l0 = 0.f, l1 = 0.f;
    float O[8][4];
#pragma unroll
    for (int nt = 0; nt < 8; nt++)
#pragma unroll
        for (int i = 0; i < 4; i++) O[nt][i] = 0.f;

    for (int j0 = 0; j0 < SS; j0 += 64) {
        __syncthreads();
#pragma unroll
        for (int i = 0; i < 2; i++) {
            const int idx = i * 256 + t;
            const int r = idx >> 3, cp = (idx & 7) * 4;
            *(uint4*)&KsH[r][cp] = *(const uint4*)&Kh[(size_t)(j0 + r) * DD2 + cp];
            *(uint4*)&KsL[r][cp] = *(const uint4*)&Kl[(size_t)(j0 + r) * DD2 + cp];
        }
#pragma unroll
        for (int i = 0; i < 2; i++) {
            const int idx = i * 256 + t;
            const int r = idx >> 4, c = (idx & 15) * 4;
            *(uint4*)&VsH[r][c] = *(const uint4*)&Vh[(size_t)(j0 / 2 + r) * DD + c];
            *(uint4*)&VsL[r][c] = *(const uint4*)&Vl[(size_t)(j0 / 2 + r) * DD + c];
        }
        if (t < 64) pk_s[t] = g_packed[b * SS + j0 + t];
        __syncthreads();

        // S = Q K^T
        float S[8][4];
#pragma unroll
        for (int nt = 0; nt < 8; nt++) {
#pragma unroll
            for (int i = 0; i < 4; i++) S[nt][i] = 0.f;
#pragma unroll
            for (int ks = 0; ks < 4; ks++) {
                const unsigned bh0 = KsH[nt * 8 + g][ks * 8 + tig];
                const unsigned bh1 = KsH[nt * 8 + g][ks * 8 + 4 + tig];
                const unsigned bl0 = KsL[nt * 8 + g][ks * 8 + tig];
                const unsigned bl1 = KsL[nt * 8 + g][ks * 8 + 4 + tig];
                mma_bf16(S[nt], qh[ks], bh0, bh1);
                mma_bf16(S[nt], ql[ks], bh0, bh1);
                mma_bf16(S[nt], qh[ks], bl0, bl1);
            }
        }

        // bias + row max
        float mloc0 = -1e30f, mloc1 = -1e30f;
#pragma unroll
        for (int nt = 0; nt < 8; nt++) {
            const unsigned cp0 = pk_s[nt * 8 + tig * 2];
            const unsigned cp1 = pk_s[nt * 8 + tig * 2 + 1];
            S[nt][0] = sbias(S[nt][0], rp0, cp0);
            S[nt][1] = sbias(S[nt][1], rp0, cp1);
            S[nt][2] = sbias(S[nt][2], rp1, cp0);
            S[nt][3] = sbias(S[nt][3], rp1, cp1);
            mloc0 = fmaxf(mloc0, fmaxf(S[nt][0], S[nt][1]));
            mloc1 = fmaxf(mloc1, fmaxf(S[nt][2], S[nt][3]));
        }
        mloc0 = fmaxf(mloc0, __shfl_xor_sync(0xffffffffu, mloc0, 1));
        mloc0 = fmaxf(mloc0, __shfl_xor_sync(0xffffffffu, mloc0, 2));
        mloc1 = fmaxf(mloc1, __shfl_xor_sync(0xffffffffu, mloc1, 1));
        mloc1 = fmaxf(mloc1, __shfl_xor_sync(0xffffffffu, mloc1, 2));

        const float mn0 = fmaxf(m0, mloc0), mn1 = fmaxf(m1, mloc1);
        float ps0 = 0.f, ps1 = 0.f;
#pragma unroll
        for (int nt = 0; nt < 8; nt++) {
            S[nt][0] = __expf(S[nt][0] - mn0); ps0 += S[nt][0];
            S[nt][1] = __expf(S[nt][1] - mn0); ps0 += S[nt][1];
            S[nt][2] = __expf(S[nt][2] - mn1); ps1 += S[nt][2];
            S[nt][3] = __expf(S[nt][3] - mn1); ps1 += S[nt][3];
        }
        ps0 += __shfl_xor_sync(0xffffffffu, ps0, 1);
        ps0 += __shfl_xor_sync(0xffffffffu, ps0, 2);
        ps1 += __shfl_xor_sync(0xffffffffu, ps1, 1);
        ps1 += __shfl_xor_sync(0xffffffffu, ps1, 2);

        const float al0 = __expf(m0 - mn0), al1 = __expf(m1 - mn1);
        l0 = l0 * al0 + ps0;  l1 = l1 * al1 + ps1;
        m0 = mn0; m1 = mn1;
#pragma unroll
        for (int nt = 0; nt < 8; nt++) {
            O[nt][0] *= al0; O[nt][1] *= al0;
            O[nt][2] *= al1; O[nt][3] *= al1;
        }

        // PV: A-frag = own C-frag values (k16 alignment), no shuffles
#pragma unroll
        for (int kk = 0; kk < 4; kk++) {
            unsigned pah[4], pal[4];
            split2(S[2 * kk    ][0], S[2 * kk    ][1], pah[0], pal[0]);  // row g,   k lo
            split2(S[2 * kk    ][2], S[2 * kk    ][3], pah[1], pal[1]);  // row g+8, k lo
            split2(S[2 * kk + 1][0], S[2 * kk + 1][1], pah[2], pal[2]);  // row g,   k hi
            split2(S[2 * kk + 1][2], S[2 * kk + 1][3], pah[3], pal[3]);  // row g+8, k hi
#pragma unroll
            for (int nt = 0; nt < 8; nt++) {
                const unsigned vh0 = VsH[kk * 8 + tig    ][nt * 8 + g];
                const unsigned vh1 = VsH[kk * 8 + 4 + tig][nt * 8 + g];
                const unsigned vl0 = VsL[kk * 8 + tig    ][nt * 8 + g];
                const unsigned vl1 = VsL[kk * 8 + 4 + tig][nt * 8 + g];
                mma_bf16(O[nt], pah, vh0, vh1);
                mma_bf16(O[nt], pal, vh0, vh1);
                mma_bf16(O[nt], pah, vl0, vl1);
            }
        }
    }

    const float inv0 = 1.f / l0, inv1 = 1.f / l1;
    float* Obase = g_AO + (size_t)(b * SS) * DD + h * HDIM;
#pragma unroll
    for (int nt = 0; nt < 8; nt++) {
        const int col = nt * 8 + tig * 2;
        float2 o0, o1;
        o0.x = O[nt][0] * inv0; o0.y = O[nt][1] * inv0;
        o1.x = O[nt][2] * inv1; o1.y = O[nt][3] * inv1;
        *(float2*)(Obase + (size_t)row_g       * DD + col) = o0;
        *(float2*)(Obase + (size_t)(row_g + 8) * DD + col) = o1;
    }
}

// ---------------- launch ----------------------------------------------------
extern "C" void kernel_launch(void* const* d_in, const int* in_sizes, int n_in,
                              void* d_out, int out_size)
{
    (void)in_sizes; (void)n_in; (void)out_size;
    const float* query = (const float*)d_in[0];
    const float* key_  = (const float*)d_in[1];
    const float* value = (const float*)d_in[2];
    const int* fid = (const int*)d_in[3];
    const int* eid = (const int*)d_in[4];
    const int* tid = (const int*)d_in[5];
    const int* ttd = (const int*)d_in[6];
    const int* edd = (const int*)d_in[7];
    const int* rid = (const int*)d_in[8];
    const float* Wq = (const float*)d_in[9];
    const float* bq = (const float*)d_in[10];
    const float* Wk = (const float*)d_in[11];
    const float* bk = (const float*)d_in[12];
    const float* Wv = (const float*)d_in[13];
    const float* bv = (const float*)d_in[14];
    const float* Wo = (const float*)d_in[15];
    const float* bo = (const float*)d_in[16];
    float* out = (float*)d_out;

    dim3 gemm_grid(DD / 128, MTOT / 128);   // (8, 32)

    gemm_bf16x2<<<gemm_grid, 256>>>(query, TAG_EXT, Wq, bq, nullptr, TAG_Q, SCALE_ATTN);
    gemm_bf16x2<<<gemm_grid, 256>>>(key_,  TAG_EXT, Wk, bk, nullptr, TAG_K, 1.0f);
    gemm_bf16x2<<<gemm_grid, 256>>>(value, TAG_EXT, Wv, bv, nullptr, TAG_V, 1.0f);

    pack_ids_kernel<<<(MTOT + 255) / 256, 256>>>(fid, eid, tid, ttd, edd, rid, MTOT);

    attn_bf16<<<dim3(SS / 128, HH, BB), 256>>>();

    gemm_bf16x2<<<gemm_grid, 256>>>(nullptr, TAG_AO, Wo, bo, out, TAG_EXT, 1.0f);
}